// round 15
// baseline (speedup 1.0000x reference)
#include <cuda_runtime.h>
#include <cuda_bf16.h>
#include <cstdint>

// CrossAttentionModel_20684562497797 — FINAL (+ last lever: 256-bit stores)
//
// Reference math collapses: softmax over a size-1 axis == 1.0 exactly for any
// finite input; mean over heads of ones == 1.0. Output is ones((2048,2048))
// independent of all inputs -> only mandatory work: write 16 MiB of 1.0f.
//
// R14 post-mortem: identical source to R9 gave e2e 7.94 vs 6.62 -> +-1.3us
// e2e noise dominates. Kernel dur pinned at 5.57-6.40us across five distinct
// structures (STG grid-stride / TMA bulk / flat / unroll-8, grids 512-2048),
// L2 ~23-26% always. Floor = ~1.3us L2-port store time + fixed ramp.
//
// Only untried lever: sm_100+ 256-bit global stores (st.global.v8.f32).
// Halves STG count per thread (4 x STG.256 vs 8 x STG.128). Expected ~neutral
// (issue never bound), but it's the last free experiment.

static constexpr int THREADS = 256;
static constexpr int BYTES_PER_THREAD = 128;                 // 4 x 32B stores
static constexpr int BYTES_PER_CTA = THREADS * BYTES_PER_THREAD;  // 32 KiB
static constexpr int V8_PER_THREAD = 4;

__global__ __launch_bounds__(THREADS)
void fill_ones_kernel(float* __restrict__ out, int n_total) {
    // Base byte offset for this thread's first 32B chunk.
    long long base = (long long)blockIdx.x * BYTES_PER_CTA
                   + (long long)threadIdx.x * 32;
    long long total_bytes = (long long)n_total * 4;

    const float one = 1.0f;

    #pragma unroll
    for (int j = 0; j < V8_PER_THREAD; j++) {
        long long off = base + (long long)j * (THREADS * 32);
        if (off + 32 <= total_bytes) {
            float* p = (float*)((char*)out + off);
            // 256-bit store (sm_100+). 8 fp32 lanes of 1.0f.
            asm volatile(
                "st.global.v8.f32 [%0], {%1, %2, %3, %4, %5, %6, %7, %8};"
                :: "l"(p),
                   "f"(one), "f"(one), "f"(one), "f"(one),
                   "f"(one), "f"(one), "f"(one), "f"(one)
                : "memory");
        }
    }

    // Scalar tail for any residue (out_size not a multiple of the 32B chunk
    // coverage — never hit for 2048x2048). Keeps the graph a single node.
    if (blockIdx.x == 0) {
        long long covered = ((total_bytes / 32) * 32) / 4;  // floats fully covered
        int t = (int)covered + threadIdx.x;
        if (t < n_total) out[t] = 1.0f;
    }
}

extern "C" void kernel_launch(void* const* d_in, const int* in_sizes, int n_in,
                              void* d_out, int out_size) {
    (void)d_in; (void)in_sizes; (void)n_in;

    float* out = (float*)d_out;
    long long total_bytes = (long long)out_size * 4;         // 16 MiB
    int blocks = (int)((total_bytes + BYTES_PER_CTA - 1) / BYTES_PER_CTA);  // 512
    if (blocks < 1) blocks = 1;

    fill_ones_kernel<<<blocks, THREADS>>>(out, out_size);
}